// round 6
// baseline (speedup 1.0000x reference)
#include <cuda_runtime.h>
#include <cuda_bf16.h>
#include <cstdint>

// ---------------------------------------------------------------------------
// Upsampling_77214922047593 — legacy mma.sync bf16x3 (sm_103 base ISA).
//   h1 = unary(support @ W1)            65536 rows, K=512
//   h2 = unary(h1 @ W2)                 65536 rows, K=256
//   out = unary((gather(h2)+query)@W3)  262144 rows, K=256
// fp32 emulated as bf16 hi/lo split, 3 MMA passes (hh + lh + hl) on
// mma.sync.m16n8k16.bf16/f32.
// R5->R6: CTA 64x256, 256 threads (8 warps, warp 32x64), 2 CTAs/SM so one
// CTA's MMAs cover the other's staging/barrier bubble. Inner ordering = R4.
// ---------------------------------------------------------------------------

namespace {
constexpr int Mm   = 16384;
constexpr int CIN  = 512;
constexpr int COUT = 256;
constexpr float EPSv   = 1e-5f;
constexpr float SLOPEv = 0.1f;

constexpr int ROWS12 = 65536;
constexpr int ROWS3  = 262144;

constexpr int TILE_M = 64;
constexpr int KC     = 32;         // K per smem chunk
constexpr int ASTRE  = 40;         // padded row stride in bf16 elems (80B)

constexpr int A_BYTES   = TILE_M * ASTRE * 2;   // 5120  (one half: hi or lo)
constexpr int B_BYTES   = COUT   * ASTRE * 2;   // 20480
constexpr int BUF_BYTES = 2 * A_BYTES + 2 * B_BYTES;  // 51200
constexpr size_t SMEM_DYN = 2 * (size_t)BUF_BYTES;    // 102400
} // namespace

__device__ float g_h1[(size_t)ROWS12 * COUT];
__device__ float g_h2[(size_t)ROWS12 * COUT];
// pre-split, pre-transposed weights: Wt[layer][n][k]
__device__ __nv_bfloat16 g_Wth[3][COUT][CIN];
__device__ __nv_bfloat16 g_Wtl[3][COUT][CIN];

// ---------------- helpers ----------------
__device__ __forceinline__ uint32_t smem_u32(const void* p) {
    uint32_t a;
    asm("{ .reg .u64 t; cvta.to.shared.u64 t, %1; cvt.u32.u64 %0, t; }"
        : "=r"(a) : "l"(p));
    return a;
}

#define LDSM4(r, addr)                                                         \
    asm volatile("ldmatrix.sync.aligned.m8n8.x4.shared.b16 {%0,%1,%2,%3}, [%4];" \
        : "=r"((r)[0]), "=r"((r)[1]), "=r"((r)[2]), "=r"((r)[3]) : "r"(addr))

#define MMA_BF16(c, a, b0, b1)                                                 \
    asm volatile("mma.sync.aligned.m16n8k16.row.col.f32.bf16.bf16.f32 "        \
        "{%0,%1,%2,%3}, {%4,%5,%6,%7}, {%8,%9}, {%0,%1,%2,%3};"                \
        : "+f"((c)[0]), "+f"((c)[1]), "+f"((c)[2]), "+f"((c)[3])               \
        : "r"((a)[0]), "r"((a)[1]), "r"((a)[2]), "r"((a)[3]),                  \
          "r"(b0), "r"(b1))

#define CP_ASYNC8(dst, src)                                                    \
    asm volatile("cp.async.ca.shared.global [%0], [%1], 8;"                    \
        :: "r"(dst), "l"(src))
#define CP_COMMIT() asm volatile("cp.async.commit_group;" ::: "memory")
#define CP_WAIT0()  asm volatile("cp.async.wait_group 0;" ::: "memory")

__device__ __forceinline__ uint32_t pack_bf16(float a, float b) {
    __nv_bfloat162 t = __floats2bfloat162_rn(a, b);
    return *reinterpret_cast<uint32_t*>(&t);
}

// split float4 into hi/lo bf16 packed words
__device__ __forceinline__ void split4(float4 v, uint32_t h[2], uint32_t l[2]) {
    __nv_bfloat16 hx = __float2bfloat16(v.x);
    __nv_bfloat16 hy = __float2bfloat16(v.y);
    __nv_bfloat16 hz = __float2bfloat16(v.z);
    __nv_bfloat16 hw = __float2bfloat16(v.w);
    float lx = v.x - __bfloat162float(hx);
    float ly = v.y - __bfloat162float(hy);
    float lz = v.z - __bfloat162float(hz);
    float lw = v.w - __bfloat162float(hw);
    __nv_bfloat162 h01; h01.x = hx; h01.y = hy;
    __nv_bfloat162 h23; h23.x = hz; h23.y = hw;
    h[0] = *reinterpret_cast<uint32_t*>(&h01);
    h[1] = *reinterpret_cast<uint32_t*>(&h23);
    l[0] = pack_bf16(lx, ly);
    l[1] = pack_bf16(lz, lw);
}

// ---------------- weight prologue: split + transpose ----------------
__global__ void split_w_kernel(const float* __restrict__ W, int layer) {
    int k = blockIdx.x;
    int n = threadIdx.x;
    float w = W[(size_t)k * COUT + n];
    __nv_bfloat16 h = __float2bfloat16(w);
    float l = w - __bfloat162float(h);
    g_Wth[layer][n][k] = h;
    g_Wtl[layer][n][k] = __float2bfloat16(l);
}

// ---------------- main fused layer ----------------
// MODE 0: support (K=512) -> g_h1 ; MODE 1: g_h1 -> g_h2 ;
// MODE 2: query + gather(g_h2) -> out
template <int MODE>
__global__ void __launch_bounds__(256, 2)
layer_kernel(const float* __restrict__ Aext,
             const float* __restrict__ bias,
             const float* __restrict__ gamma,
             const float* __restrict__ beta,
             const int*   __restrict__ idx,
             float*       __restrict__ Oext)
{
    constexpr int K     = (MODE == 0) ? CIN : COUT;
    constexpr int NC    = K / KC;
    constexpr int LAYER = MODE;

    extern __shared__ __align__(16) char smc[];
    __shared__ int s_grow[TILE_M];

    const int tid  = threadIdx.x;
    const int wid  = tid >> 5;
    const int lane = tid & 31;
    const int rowBlk = blockIdx.x * TILE_M;

    const float* Asrc = (MODE == 1) ? g_h1 : Aext;
    float*       Odst = (MODE == 0) ? g_h1 : ((MODE == 1) ? g_h2 : Oext);

    const __nv_bfloat16* Wth = &g_Wth[LAYER][0][0];
    const __nv_bfloat16* Wtl = &g_Wtl[LAYER][0][0];

    const uint32_t sbase = smem_u32(smc);

    if (MODE == 2) {
        if (tid < TILE_M) {
            int grow = rowBlk + tid;
            s_grow[tid] = (grow >> 16) * Mm + idx[grow];
        }
        __syncthreads();
    }

    // ---- staging ----
    // A: 64 x 32 fp32 -> 512 float4, 256 threads -> 2 each
    float4 vpipe[2];
    auto ldgA = [&](int kc) {
#pragma unroll
        for (int i = 0; i < 2; i++) {
            int s  = tid + i * 256;
            int r  = s >> 3;
            int c4 = (s & 7) * 4;
            if (MODE == 2) {
                float4 q = *(const float4*)(Aext + (size_t)(rowBlk + r) * COUT + kc + c4);
                float4 g = *(const float4*)(g_h2 + (size_t)s_grow[r] * COUT + kc + c4);
                vpipe[i] = make_float4(q.x + g.x, q.y + g.y, q.z + g.z, q.w + g.w);
            } else {
                vpipe[i] = *(const float4*)(Asrc + (size_t)(rowBlk + r) * K + kc + c4);
            }
        }
    };
    auto stsA = [&](int buf) {
        char* ab = smc + buf * BUF_BYTES;
#pragma unroll
        for (int i = 0; i < 2; i++) {
            int s  = tid + i * 256;
            int r  = s >> 3;
            int c4 = (s & 7) * 4;
            uint32_t h[2], l[2];
            split4(vpipe[i], h, l);
            int off = (r * ASTRE + c4) * 2;
            *(uint2*)(ab + off)           = make_uint2(h[0], h[1]);
            *(uint2*)(ab + A_BYTES + off) = make_uint2(l[0], l[1]);
        }
    };
    // B: 256 n-rows x 8 8B-segs per half; 2048 ops/half / 256 thr = 8 each
    auto cpB = [&](int kc, int buf) {
        uint32_t bh = sbase + buf * BUF_BYTES + 2 * A_BYTES;
        uint32_t bl = bh + B_BYTES;
#pragma unroll
        for (int i = 0; i < 8; i++) {
            int q   = tid + i * 256;          // 0..2047
            int n   = q >> 3;
            int seg = q & 7;
            uint32_t doff = (uint32_t)(n * ASTRE + seg * 4) * 2;
            size_t   soff = (size_t)n * CIN + kc + seg * 4;
            CP_ASYNC8(bh + doff, Wth + soff);
            CP_ASYNC8(bl + doff, Wtl + soff);
        }
    };

    // ---- warp layout: 8 warps = 2 m-groups x 4 n-groups, warp tile 32x64 ----
    const int wr = (wid & 1) * 32;
    const int wc = (wid >> 1) * 64;

    float acc[2][8][4];
#pragma unroll
    for (int mi = 0; mi < 2; mi++)
#pragma unroll
        for (int j = 0; j < 8; j++)
#pragma unroll
            for (int c = 0; c < 4; c++) acc[mi][j][c] = 0.f;

    // ldmatrix lane addressing
    const int a_r  = (lane & 15);
    const int a_kh = (lane >> 4) * 8;
    const int b_r  = ((lane >> 4) & 1) * 8 + (lane & 7);
    const int b_kh = ((lane >> 3) & 1) * 8;

    // ---- prime chunk 0 ----
    ldgA(0);
    cpB(0, 0);
    CP_COMMIT();
    stsA(0);

#pragma unroll 1
    for (int c = 0; c < NC; c++) {
        const int cb = c & 1;
        const bool more = (c + 1 < NC);

        if (more) ldgA((c + 1) * KC);    // LDGs in flight across the wait
        CP_WAIT0();
        __syncthreads();
        if (more) {
            cpB((c + 1) * KC, (c + 1) & 1);
            CP_COMMIT();
        }

        // ---- MMAs on buffer cb (R4 ordering) ----
        const uint32_t aH = sbase + cb * BUF_BYTES;
        const uint32_t bH = aH + 2 * A_BYTES;
#pragma unroll
        for (int ks = 0; ks < 2; ks++) {
            const int k0 = ks * 16;
            uint32_t ah[2][4], al[2][4];
#pragma unroll
            for (int mi = 0; mi < 2; mi++) {
                uint32_t ad = aH + (uint32_t)((wr + mi * 16 + a_r) * ASTRE + k0 + a_kh) * 2;
                LDSM4(ah[mi], ad);
                LDSM4(al[mi], ad + A_BYTES);
            }
#pragma unroll
            for (int jp = 0; jp < 4; jp++) {
                uint32_t bhr[4], blr[4];
                uint32_t bd = bH + (uint32_t)((wc + jp * 16 + b_r) * ASTRE + k0 + b_kh) * 2;
                LDSM4(bhr, bd);
                LDSM4(blr, bd + B_BYTES);
#pragma unroll
                for (int mi = 0; mi < 2; mi++)
#pragma unroll
                    for (int jj = 0; jj < 2; jj++) {
                        float* C = acc[mi][jp * 2 + jj];
                        MMA_BF16(C, ah[mi], bhr[jj * 2], bhr[jj * 2 + 1]);
                        MMA_BF16(C, al[mi], bhr[jj * 2], bhr[jj * 2 + 1]);
                        MMA_BF16(C, ah[mi], blr[jj * 2], blr[jj * 2 + 1]);
                    }
            }
        }

        if (more) stsA((c + 1) & 1);
    }

    // ---- fused epilogue: +bias, GroupNorm(8ch = one n8 tile), affine, lrelu
    const int qlane = lane & 3;
#pragma unroll
    for (int j = 0; j < 8; j++) {
        const int col = wc + j * 8 + 2 * qlane;
        const float2 bb = *reinterpret_cast<const float2*>(bias + col);
        const float2 gg = *reinterpret_cast<const float2*>(gamma + col);
        const float2 be = *reinterpret_cast<const float2*>(beta + col);
#pragma unroll
        for (int mi = 0; mi < 2; mi++) {
            float v0 = acc[mi][j][0] + bb.x;
            float v1 = acc[mi][j][1] + bb.y;
            float v2 = acc[mi][j][2] + bb.x;
            float v3 = acc[mi][j][3] + bb.y;

            float s0 = v0 + v1,           s1 = v2 + v3;
            float t0 = v0 * v0 + v1 * v1, t1 = v2 * v2 + v3 * v3;
            s0 += __shfl_xor_sync(0xffffffffu, s0, 1);
            s0 += __shfl_xor_sync(0xffffffffu, s0, 2);
            s1 += __shfl_xor_sync(0xffffffffu, s1, 1);
            s1 += __shfl_xor_sync(0xffffffffu, s1, 2);
            t0 += __shfl_xor_sync(0xffffffffu, t0, 1);
            t0 += __shfl_xor_sync(0xffffffffu, t0, 2);
            t1 += __shfl_xor_sync(0xffffffffu, t1, 1);
            t1 += __shfl_xor_sync(0xffffffffu, t1, 2);

            const float m0 = s0 * 0.125f, m1 = s1 * 0.125f;
            const float r0 = rsqrtf(fmaxf(t0 * 0.125f - m0 * m0, 0.f) + EPSv);
            const float r1 = rsqrtf(fmaxf(t1 * 0.125f - m1 * m1, 0.f) + EPSv);

            float y0 = (v0 - m0) * r0 * gg.x + be.x;
            float y1 = (v1 - m0) * r0 * gg.y + be.y;
            float y2 = (v2 - m1) * r1 * gg.x + be.x;
            float y3 = (v3 - m1) * r1 * gg.y + be.y;
            y0 = (y0 >= 0.f) ? y0 : SLOPEv * y0;
            y1 = (y1 >= 0.f) ? y1 : SLOPEv * y1;
            y2 = (y2 >= 0.f) ? y2 : SLOPEv * y2;
            y3 = (y3 >= 0.f) ? y3 : SLOPEv * y3;

            const size_t row = (size_t)rowBlk + wr + mi * 16 + (lane >> 2);
            *reinterpret_cast<float2*>(Odst + row * COUT + col) =
                make_float2(y0, y1);
            *reinterpret_cast<float2*>(Odst + (row + 8) * COUT + col) =
                make_float2(y2, y3);
        }
    }
}

extern "C" void kernel_launch(void* const* d_in, const int* in_sizes, int n_in,
                              void* d_out, int out_size)
{
    (void)in_sizes; (void)n_in; (void)out_size;
    const float* query   = (const float*)d_in[0];
    const float* support = (const float*)d_in[1];
    const int*   idx     = (const int*)d_in[2];
    const float* W1  = (const float*)d_in[3];
    const float* b1  = (const float*)d_in[4];
    const float* g1  = (const float*)d_in[5];
    const float* be1 = (const float*)d_in[6];
    const float* W2  = (const float*)d_in[7];
    const float* b2  = (const float*)d_in[8];
    const float* g2  = (const float*)d_in[9];
    const float* be2 = (const float*)d_in[10];
    const float* W3  = (const float*)d_in[11];
    const float* b3  = (const float*)d_in[12];
    const float* g3  = (const float*)d_in[13];
    const float* be3 = (const float*)d_in[14];
    float* out = (float*)d_out;

    split_w_kernel<<<CIN,  COUT>>>(W1, 0);
    split_w_kernel<<<COUT, COUT>>>(W2, 1);
    split_w_kernel<<<COUT, COUT>>>(W3, 2);

    cudaFuncSetAttribute(layer_kernel<0>,
        cudaFuncAttributeMaxDynamicSharedMemorySize, (int)SMEM_DYN);
    cudaFuncSetAttribute(layer_kernel<1>,
        cudaFuncAttributeMaxDynamicSharedMemorySize, (int)SMEM_DYN);
    cudaFuncSetAttribute(layer_kernel<2>,
        cudaFuncAttributeMaxDynamicSharedMemorySize, (int)SMEM_DYN);

    layer_kernel<0><<<ROWS12 / TILE_M, 256, SMEM_DYN>>>(
        support, b1, g1, be1, nullptr, nullptr);
    layer_kernel<1><<<ROWS12 / TILE_M, 256, SMEM_DYN>>>(
        nullptr, b2, g2, be2, nullptr, nullptr);
    layer_kernel<2><<<ROWS3 / TILE_M, 256, SMEM_DYN>>>(
        query, b3, g3, be3, idx, out);
}

// round 7
// speedup vs baseline: 1.3998x; 1.3998x over previous
#include <cuda_runtime.h>
#include <cuda_fp16.h>
#include <cstdint>

// ---------------------------------------------------------------------------
// Upsampling_77214922047593 — legacy mma.sync fp16x2 (sm_103 base ISA).
//   h1 = unary(support @ W1)            65536 rows, K=512
//   h2 = unary(h1 @ W2)                 65536 rows, K=256
//   out = unary((gather(h2)+query)@W3)  262144 rows, K=256
// fp32 emulated as fp16 hi/lo split of A, fp16 B: 2 MMA passes
// (a_hi*b + a_lo*b) on mma.sync.m16n8k16.f16/f32 (dropped term a*b_lo
// ~2^-11.8 rel/layer -> ~5e-4 total, under the 1e-3 bound).
// R4 config: CTA 128x256, 512 thr (16 warps, warp 32x64), double-buffered
// smem, cp.async fp16 weights (pre-rounded+transposed), fused
// GroupNorm(32 groups of 8) + affine + leaky-relu epilogue.
// ---------------------------------------------------------------------------

namespace {
constexpr int Mm   = 16384;
constexpr int CIN  = 512;
constexpr int COUT = 256;
constexpr float EPSv   = 1e-5f;
constexpr float SLOPEv = 0.1f;

constexpr int ROWS12 = 65536;
constexpr int ROWS3  = 262144;

constexpr int TILE_M = 128;
constexpr int KC     = 32;         // K per smem chunk
constexpr int ASTRE  = 40;         // padded row stride in fp16 elems (80B)

constexpr int A_BYTES   = TILE_M * ASTRE * 2;   // 10240 (one half: hi or lo)
constexpr int B_BYTES   = COUT   * ASTRE * 2;   // 20480 (hi only)
constexpr int BUF_BYTES = 2 * A_BYTES + B_BYTES;      // 40960
constexpr size_t SMEM_DYN = 2 * (size_t)BUF_BYTES;    // 81920
} // namespace

__device__ float g_h1[(size_t)ROWS12 * COUT];
__device__ float g_h2[(size_t)ROWS12 * COUT];
// pre-rounded, pre-transposed weights: Wt[layer][n][k], fp16
__device__ __half g_Wth[3][COUT][CIN];

// ---------------- helpers ----------------
__device__ __forceinline__ uint32_t smem_u32(const void* p) {
    uint32_t a;
    asm("{ .reg .u64 t; cvta.to.shared.u64 t, %1; cvt.u32.u64 %0, t; }"
        : "=r"(a) : "l"(p));
    return a;
}

#define LDSM4(r, addr)                                                         \
    asm volatile("ldmatrix.sync.aligned.m8n8.x4.shared.b16 {%0,%1,%2,%3}, [%4];" \
        : "=r"((r)[0]), "=r"((r)[1]), "=r"((r)[2]), "=r"((r)[3]) : "r"(addr))

#define MMA_F16(c, a, b0, b1)                                                  \
    asm volatile("mma.sync.aligned.m16n8k16.row.col.f32.f16.f16.f32 "          \
        "{%0,%1,%2,%3}, {%4,%5,%6,%7}, {%8,%9}, {%0,%1,%2,%3};"                \
        : "+f"((c)[0]), "+f"((c)[1]), "+f"((c)[2]), "+f"((c)[3])               \
        : "r"((a)[0]), "r"((a)[1]), "r"((a)[2]), "r"((a)[3]),                  \
          "r"(b0), "r"(b1))

#define CP_ASYNC8(dst, src)                                                    \
    asm volatile("cp.async.ca.shared.global [%0], [%1], 8;"                    \
        :: "r"(dst), "l"(src))
#define CP_COMMIT() asm volatile("cp.async.commit_group;" ::: "memory")
#define CP_WAIT0()  asm volatile("cp.async.wait_group 0;" ::: "memory")

// split float4 into hi/lo fp16 packed words
__device__ __forceinline__ void split4h(float4 v, uint32_t h[2], uint32_t l[2]) {
    __half2 h01 = __floats2half2_rn(v.x, v.y);
    __half2 h23 = __floats2half2_rn(v.z, v.w);
    float lx = v.x - __half2float(__low2half(h01));
    float ly = v.y - __half2float(__high2half(h01));
    float lz = v.z - __half2float(__low2half(h23));
    float lw = v.w - __half2float(__high2half(h23));
    __half2 l01 = __floats2half2_rn(lx, ly);
    __half2 l23 = __floats2half2_rn(lz, lw);
    h[0] = *reinterpret_cast<uint32_t*>(&h01);
    h[1] = *reinterpret_cast<uint32_t*>(&h23);
    l[0] = *reinterpret_cast<uint32_t*>(&l01);
    l[1] = *reinterpret_cast<uint32_t*>(&l23);
}

// ---------------- weight prologue: round + transpose ----------------
__global__ void split_w_kernel(const float* __restrict__ W, int layer) {
    int k = blockIdx.x;
    int n = threadIdx.x;
    g_Wth[layer][n][k] = __float2half_rn(W[(size_t)k * COUT + n]);
}

// ---------------- main fused layer ----------------
// MODE 0: support (K=512) -> g_h1 ; MODE 1: g_h1 -> g_h2 ;
// MODE 2: query + gather(g_h2) -> out
template <int MODE>
__global__ void __launch_bounds__(512, 1)
layer_kernel(const float* __restrict__ Aext,
             const float* __restrict__ bias,
             const float* __restrict__ gamma,
             const float* __restrict__ beta,
             const int*   __restrict__ idx,
             float*       __restrict__ Oext)
{
    constexpr int K     = (MODE == 0) ? CIN : COUT;
    constexpr int NC    = K / KC;
    constexpr int LAYER = MODE;

    extern __shared__ __align__(16) char smc[];
    __shared__ int s_grow[TILE_M];

    const int tid  = threadIdx.x;
    const int wid  = tid >> 5;
    const int lane = tid & 31;
    const int rowBlk = blockIdx.x * TILE_M;

    const float* Asrc = (MODE == 1) ? g_h1 : Aext;
    float*       Odst = (MODE == 0) ? g_h1 : ((MODE == 1) ? g_h2 : Oext);

    const __half* Wth = &g_Wth[LAYER][0][0];

    const uint32_t sbase = smem_u32(smc);

    if (MODE == 2) {
        if (tid < TILE_M) {
            int grow = rowBlk + tid;
            s_grow[tid] = (grow >> 16) * Mm + idx[grow];
        }
        __syncthreads();
    }

    // ---- staging ----
    // A: 128 x 32 fp32 -> 1024 float4, 512 threads -> 2 each
    float4 vpipe[2];
    auto ldgA = [&](int kc) {
#pragma unroll
        for (int i = 0; i < 2; i++) {
            int s  = tid + i * 512;
            int r  = s >> 3;
            int c4 = (s & 7) * 4;
            if (MODE == 2) {
                float4 q = *(const float4*)(Aext + (size_t)(rowBlk + r) * COUT + kc + c4);
                float4 g = *(const float4*)(g_h2 + (size_t)s_grow[r] * COUT + kc + c4);
                vpipe[i] = make_float4(q.x + g.x, q.y + g.y, q.z + g.z, q.w + g.w);
            } else {
                vpipe[i] = *(const float4*)(Asrc + (size_t)(rowBlk + r) * K + kc + c4);
            }
        }
    };
    auto stsA = [&](int buf) {
        char* ab = smc + buf * BUF_BYTES;
#pragma unroll
        for (int i = 0; i < 2; i++) {
            int s  = tid + i * 512;
            int r  = s >> 3;
            int c4 = (s & 7) * 4;
            uint32_t h[2], l[2];
            split4h(vpipe[i], h, l);
            int off = (r * ASTRE + c4) * 2;
            *(uint2*)(ab + off)           = make_uint2(h[0], h[1]);
            *(uint2*)(ab + A_BYTES + off) = make_uint2(l[0], l[1]);
        }
    };
    // B (hi only): 256 n-rows x 8 8B-segs = 2048 segs / 512 thr = 4 each
    auto cpB = [&](int kc, int buf) {
        uint32_t bh = sbase + buf * BUF_BYTES + 2 * A_BYTES;
#pragma unroll
        for (int i = 0; i < 4; i++) {
            int q   = tid + i * 512;          // 0..2047
            int n   = q >> 3;
            int seg = q & 7;
            uint32_t doff = (uint32_t)(n * ASTRE + seg * 4) * 2;
            size_t   soff = (size_t)n * CIN + kc + seg * 4;
            CP_ASYNC8(bh + doff, Wth + soff);
        }
    };

    // ---- warp layout: 16 warps = 4 m-groups x 4 n-groups, warp 32x64 ----
    const int wm = wid & 3;
    const int wn = wid >> 2;
    const int wr = wm * 32;
    const int wc = wn * 64;

    float acc[2][8][4];
#pragma unroll
    for (int mi = 0; mi < 2; mi++)
#pragma unroll
        for (int j = 0; j < 8; j++)
#pragma unroll
            for (int c = 0; c < 4; c++) acc[mi][j][c] = 0.f;

    // ldmatrix lane addressing
    const int a_r  = (lane & 15);
    const int a_kh = (lane >> 4) * 8;
    const int b_r  = ((lane >> 4) & 1) * 8 + (lane & 7);
    const int b_kh = ((lane >> 3) & 1) * 8;

    // ---- prime chunk 0 ----
    ldgA(0);
    cpB(0, 0);
    CP_COMMIT();
    stsA(0);

#pragma unroll 1
    for (int c = 0; c < NC; c++) {
        const int cb = c & 1;
        const bool more = (c + 1 < NC);

        if (more) ldgA((c + 1) * KC);    // LDGs in flight across the wait
        CP_WAIT0();
        __syncthreads();
        if (more) {
            cpB((c + 1) * KC, (c + 1) & 1);
            CP_COMMIT();
        }

        // ---- MMAs on buffer cb (R4 ordering, 2 passes) ----
        const uint32_t aH = sbase + cb * BUF_BYTES;
        const uint32_t bH = aH + 2 * A_BYTES;
#pragma unroll
        for (int ks = 0; ks < 2; ks++) {
            const int k0 = ks * 16;
            uint32_t ah[2][4], al[2][4];
#pragma unroll
            for (int mi = 0; mi < 2; mi++) {
                uint32_t ad = aH + (uint32_t)((wr + mi * 16 + a_r) * ASTRE + k0 + a_kh) * 2;
                LDSM4(ah[mi], ad);
                LDSM4(al[mi], ad + A_BYTES);
            }
#pragma unroll
            for (int jp = 0; jp < 4; jp++) {
                uint32_t bhr[4];
                uint32_t bd = bH + (uint32_t)((wc + jp * 16 + b_r) * ASTRE + k0 + b_kh) * 2;
                LDSM4(bhr, bd);
#pragma unroll
                for (int mi = 0; mi < 2; mi++)
#pragma unroll
                    for (int jj = 0; jj < 2; jj++) {
                        float* C = acc[mi][jp * 2 + jj];
                        MMA_F16(C, ah[mi], bhr[jj * 2], bhr[jj * 2 + 1]);
                        MMA_F16(C, al[mi], bhr[jj * 2], bhr[jj * 2 + 1]);
                    }
            }
        }

        if (more) stsA((c + 1) & 1);
    }

    // ---- fused epilogue: +bias, GroupNorm(8ch = one n8 tile), affine, lrelu
    const int qlane = lane & 3;
#pragma unroll
    for (int j = 0; j < 8; j++) {
        const int col = wc + j * 8 + 2 * qlane;
        const float2 bb = *reinterpret_cast<const float2*>(bias + col);
        const float2 gg = *reinterpret_cast<const float2*>(gamma + col);
        const float2 be = *reinterpret_cast<const float2*>(beta + col);
#pragma unroll
        for (int mi = 0; mi < 2; mi++) {
            float v0 = acc[mi][j][0] + bb.x;
            float v1 = acc[mi][j][1] + bb.y;
            float v2 = acc[mi][j][2] + bb.x;
            float v3 = acc[mi][j][3] + bb.y;

            float s0 = v0 + v1,           s1 = v2 + v3;
            float t0 = v0 * v0 + v1 * v1, t1 = v2 * v2 + v3 * v3;
            s0 += __shfl_xor_sync(0xffffffffu, s0, 1);
            s0 += __shfl_xor_sync(0xffffffffu, s0, 2);
            s1 += __shfl_xor_sync(0xffffffffu, s1, 1);
            s1 += __shfl_xor_sync(0xffffffffu, s1, 2);
            t0 += __shfl_xor_sync(0xffffffffu, t0, 1);
            t0 += __shfl_xor_sync(0xffffffffu, t0, 2);
            t1 += __shfl_xor_sync(0xffffffffu, t1, 1);
            t1 += __shfl_xor_sync(0xffffffffu, t1, 2);

            const float m0 = s0 * 0.125f, m1 = s1 * 0.125f;
            const float r0 = rsqrtf(fmaxf(t0 * 0.125f - m0 * m0, 0.f) + EPSv);
            const float r1 = rsqrtf(fmaxf(t1 * 0.125f - m1 * m1, 0.f) + EPSv);

            float y0 = (v0 - m0) * r0 * gg.x + be.x;
            float y1 = (v1 - m0) * r0 * gg.y + be.y;
            float y2 = (v2 - m1) * r1 * gg.x + be.x;
            float y3 = (v3 - m1) * r1 * gg.y + be.y;
            y0 = (y0 >= 0.f) ? y0 : SLOPEv * y0;
            y1 = (y1 >= 0.f) ? y1 : SLOPEv * y1;
            y2 = (y2 >= 0.f) ? y2 : SLOPEv * y2;
            y3 = (y3 >= 0.f) ? y3 : SLOPEv * y3;

            const size_t row = (size_t)rowBlk + wr + mi * 16 + (lane >> 2);
            *reinterpret_cast<float2*>(Odst + row * COUT + col) =
                make_float2(y0, y1);
            *reinterpret_cast<float2*>(Odst + (row + 8) * COUT + col) =
                make_float2(y2, y3);
        }
    }
}

extern "C" void kernel_launch(void* const* d_in, const int* in_sizes, int n_in,
                              void* d_out, int out_size)
{
    (void)in_sizes; (void)n_in; (void)out_size;
    const float* query   = (const float*)d_in[0];
    const float* support = (const float*)d_in[1];
    const int*   idx     = (const int*)d_in[2];
    const float* W1  = (const float*)d_in[3];
    const float* b1  = (const float*)d_in[4];
    const float* g1  = (const float*)d_in[5];
    const float* be1 = (const float*)d_in[6];
    const float* W2  = (const float*)d_in[7];
    const float* b2  = (const float*)d_in[8];
    const float* g2  = (const float*)d_in[9];
    const float* be2 = (const float*)d_in[10];
    const float* W3  = (const float*)d_in[11];
    const float* b3  = (const float*)d_in[12];
    const float* g3  = (const float*)d_in[13];
    const float* be3 = (const float*)d_in[14];
    float* out = (float*)d_out;

    split_w_kernel<<<CIN,  COUT>>>(W1, 0);
    split_w_kernel<<<COUT, COUT>>>(W2, 1);
    split_w_kernel<<<COUT, COUT>>>(W3, 2);

    cudaFuncSetAttribute(layer_kernel<0>,
        cudaFuncAttributeMaxDynamicSharedMemorySize, (int)SMEM_DYN);
    cudaFuncSetAttribute(layer_kernel<1>,
        cudaFuncAttributeMaxDynamicSharedMemorySize, (int)SMEM_DYN);
    cudaFuncSetAttribute(layer_kernel<2>,
        cudaFuncAttributeMaxDynamicSharedMemorySize, (int)SMEM_DYN);

    layer_kernel<0><<<ROWS12 / TILE_M, 512, SMEM_DYN>>>(
        support, b1, g1, be1, nullptr, nullptr);
    layer_kernel<1><<<ROWS12 / TILE_M, 512, SMEM_DYN>>>(
        nullptr, b2, g2, be2, nullptr, nullptr);
    layer_kernel<2><<<ROWS3 / TILE_M, 512, SMEM_DYN>>>(
        query, b3, g3, be3, idx, out);
}

// round 8
// speedup vs baseline: 1.4736x; 1.0528x over previous
#include <cuda_runtime.h>
#include <cuda_fp16.h>
#include <cstdint>

// ---------------------------------------------------------------------------
// Upsampling_77214922047593 — legacy mma.sync fp16x2 (sm_103 base ISA).
//   h1 = unary(support @ W1)            65536 rows, K=512
//   h2 = unary(h1 @ W2)                 65536 rows, K=256
//   out = unary((gather(h2)+query)@W3)  262144 rows, K=256
// fp32 emulated as fp16 hi/lo split of A, fp16 B: 2 MMA passes
// (a_hi*b + a_lo*b) on mma.sync.m16n8k16.f16/f32.
// R7->R8: (1) per-jp pass-major MMA ordering: 4 independent hi-MMAs then
// 4 lo-MMAs (same-acc reuse distance 1 -> 4, covers ~20cyc HMMA latency),
// no extra registers, no B prefetch. (2) KC 32 -> 64: half the
// barrier/staging tails per layer.
// ---------------------------------------------------------------------------

namespace {
constexpr int Mm   = 16384;
constexpr int CIN  = 512;
constexpr int COUT = 256;
constexpr float EPSv   = 1e-5f;
constexpr float SLOPEv = 0.1f;

constexpr int ROWS12 = 65536;
constexpr int ROWS3  = 262144;

constexpr int TILE_M = 128;
constexpr int KC     = 64;         // K per smem chunk
constexpr int ASTRE  = 72;         // padded row stride in fp16 elems (144B)

constexpr int A_BYTES   = TILE_M * ASTRE * 2;   // 18432 (one half: hi or lo)
constexpr int B_BYTES   = COUT   * ASTRE * 2;   // 36864 (hi only)
constexpr int BUF_BYTES = 2 * A_BYTES + B_BYTES;      // 73728
constexpr size_t SMEM_DYN = 2 * (size_t)BUF_BYTES;    // 147456
} // namespace

__device__ float g_h1[(size_t)ROWS12 * COUT];
__device__ float g_h2[(size_t)ROWS12 * COUT];
// pre-rounded, pre-transposed weights: Wt[layer][n][k], fp16
__device__ __half g_Wth[3][COUT][CIN];

// ---------------- helpers ----------------
__device__ __forceinline__ uint32_t smem_u32(const void* p) {
    uint32_t a;
    asm("{ .reg .u64 t; cvta.to.shared.u64 t, %1; cvt.u32.u64 %0, t; }"
        : "=r"(a) : "l"(p));
    return a;
}

#define LDSM4(r, addr)                                                         \
    asm volatile("ldmatrix.sync.aligned.m8n8.x4.shared.b16 {%0,%1,%2,%3}, [%4];" \
        : "=r"((r)[0]), "=r"((r)[1]), "=r"((r)[2]), "=r"((r)[3]) : "r"(addr))

#define MMA_F16(c, a, b0, b1)                                                  \
    asm volatile("mma.sync.aligned.m16n8k16.row.col.f32.f16.f16.f32 "          \
        "{%0,%1,%2,%3}, {%4,%5,%6,%7}, {%8,%9}, {%0,%1,%2,%3};"                \
        : "+f"((c)[0]), "+f"((c)[1]), "+f"((c)[2]), "+f"((c)[3])               \
        : "r"((a)[0]), "r"((a)[1]), "r"((a)[2]), "r"((a)[3]),                  \
          "r"(b0), "r"(b1))

#define CP_ASYNC8(dst, src)                                                    \
    asm volatile("cp.async.ca.shared.global [%0], [%1], 8;"                    \
        :: "r"(dst), "l"(src))
#define CP_COMMIT() asm volatile("cp.async.commit_group;" ::: "memory")
#define CP_WAIT0()  asm volatile("cp.async.wait_group 0;" ::: "memory")

// split float4 into hi/lo fp16 packed words
__device__ __forceinline__ void split4h(float4 v, uint32_t h[2], uint32_t l[2]) {
    __half2 h01 = __floats2half2_rn(v.x, v.y);
    __half2 h23 = __floats2half2_rn(v.z, v.w);
    float lx = v.x - __half2float(__low2half(h01));
    float ly = v.y - __half2float(__high2half(h01));
    float lz = v.z - __half2float(__low2half(h23));
    float lw = v.w - __half2float(__high2half(h23));
    __half2 l01 = __floats2half2_rn(lx, ly);
    __half2 l23 = __floats2half2_rn(lz, lw);
    h[0] = *reinterpret_cast<uint32_t*>(&h01);
    h[1] = *reinterpret_cast<uint32_t*>(&h23);
    l[0] = *reinterpret_cast<uint32_t*>(&l01);
    l[1] = *reinterpret_cast<uint32_t*>(&l23);
}

// ---------------- weight prologue: round + transpose ----------------
__global__ void split_w_kernel(const float* __restrict__ W, int layer) {
    int k = blockIdx.x;
    int n = threadIdx.x;
    g_Wth[layer][n][k] = __float2half_rn(W[(size_t)k * COUT + n]);
}

// ---------------- main fused layer ----------------
// MODE 0: support (K=512) -> g_h1 ; MODE 1: g_h1 -> g_h2 ;
// MODE 2: query + gather(g_h2) -> out
template <int MODE>
__global__ void __launch_bounds__(512, 1)
layer_kernel(const float* __restrict__ Aext,
             const float* __restrict__ bias,
             const float* __restrict__ gamma,
             const float* __restrict__ beta,
             const int*   __restrict__ idx,
             float*       __restrict__ Oext)
{
    constexpr int K     = (MODE == 0) ? CIN : COUT;
    constexpr int NC    = K / KC;
    constexpr int LAYER = MODE;

    extern __shared__ __align__(16) char smc[];
    __shared__ int s_grow[TILE_M];

    const int tid  = threadIdx.x;
    const int wid  = tid >> 5;
    const int lane = tid & 31;
    const int rowBlk = blockIdx.x * TILE_M;

    const float* Asrc = (MODE == 1) ? g_h1 : Aext;
    float*       Odst = (MODE == 0) ? g_h1 : ((MODE == 1) ? g_h2 : Oext);

    const __half* Wth = &g_Wth[LAYER][0][0];

    const uint32_t sbase = smem_u32(smc);

    if (MODE == 2) {
        if (tid < TILE_M) {
            int grow = rowBlk + tid;
            s_grow[tid] = (grow >> 16) * Mm + idx[grow];
        }
        __syncthreads();
    }

    // ---- staging ----
    // A: 128 x 64 fp32 -> 2048 float4, 512 threads -> 4 each
    float4 vpipe[4];
    auto ldgA = [&](int kc) {
#pragma unroll
        for (int i = 0; i < 4; i++) {
            int s  = tid + i * 512;
            int r  = s >> 4;
            int c4 = (s & 15) * 4;
            if (MODE == 2) {
                float4 q = *(const float4*)(Aext + (size_t)(rowBlk + r) * COUT + kc + c4);
                float4 g = *(const float4*)(g_h2 + (size_t)s_grow[r] * COUT + kc + c4);
                vpipe[i] = make_float4(q.x + g.x, q.y + g.y, q.z + g.z, q.w + g.w);
            } else {
                vpipe[i] = *(const float4*)(Asrc + (size_t)(rowBlk + r) * K + kc + c4);
            }
        }
    };
    auto stsA = [&](int buf) {
        char* ab = smc + buf * BUF_BYTES;
#pragma unroll
        for (int i = 0; i < 4; i++) {
            int s  = tid + i * 512;
            int r  = s >> 4;
            int c4 = (s & 15) * 4;
            uint32_t h[2], l[2];
            split4h(vpipe[i], h, l);
            int off = (r * ASTRE + c4) * 2;
            *(uint2*)(ab + off)           = make_uint2(h[0], h[1]);
            *(uint2*)(ab + A_BYTES + off) = make_uint2(l[0], l[1]);
        }
    };
    // B (hi only): 256 n-rows x 16 8B-segs = 4096 segs / 512 thr = 8 each
    auto cpB = [&](int kc, int buf) {
        uint32_t bh = sbase + buf * BUF_BYTES + 2 * A_BYTES;
#pragma unroll
        for (int i = 0; i < 8; i++) {
            int q   = tid + i * 512;          // 0..4095
            int n   = q >> 4;
            int seg = q & 15;
            uint32_t doff = (uint32_t)(n * ASTRE + seg * 4) * 2;
            size_t   soff = (size_t)n * CIN + kc + seg * 4;
            CP_ASYNC8(bh + doff, Wth + soff);
        }
    };

    // ---- warp layout: 16 warps = 4 m-groups x 4 n-groups, warp 32x64 ----
    const int wm = wid & 3;
    const int wn = wid >> 2;
    const int wr = wm * 32;
    const int wc = wn * 64;

    float acc[2][8][4];
#pragma unroll
    for (int mi = 0; mi < 2; mi++)
#pragma unroll
        for (int j = 0; j < 8; j++)
#pragma unroll
            for (int c = 0; c < 4; c++) acc[mi][j][c] = 0.f;

    // ldmatrix lane addressing
    const int a_r  = (lane & 15);
    const int a_kh = (lane >> 4) * 8;
    const int b_r  = ((lane >> 4) & 1) * 8 + (lane & 7);
    const int b_kh = ((lane >> 3) & 1) * 8;

    // ---- prime chunk 0 ----
    ldgA(0);
    cpB(0, 0);
    CP_COMMIT();
    stsA(0);

#pragma unroll 1
    for (int c = 0; c < NC; c++) {
        const int cb = c & 1;
        const bool more = (c + 1 < NC);

        if (more) ldgA((c + 1) * KC);    // LDGs in flight across the wait
        CP_WAIT0();
        __syncthreads();
        if (more) {
            cpB((c + 1) * KC, (c + 1) & 1);
            CP_COMMIT();
        }

        // ---- MMAs on buffer cb: per-jp pass-major (hi x4 then lo x4) ----
        const uint32_t aH = sbase + cb * BUF_BYTES;
        const uint32_t bH = aH + 2 * A_BYTES;
#pragma unroll
        for (int ks = 0; ks < 4; ks++) {
            const int k0 = ks * 16;
            uint32_t ah[2][4], al[2][4];
#pragma unroll
            for (int mi = 0; mi < 2; mi++) {
                uint32_t ad = aH + (uint32_t)((wr + mi * 16 + a_r) * ASTRE + k0 + a_kh) * 2;
                LDSM4(ah[mi], ad);
                LDSM4(al[mi], ad + A_BYTES);
            }
#pragma unroll
            for (int jp = 0; jp < 4; jp++) {
                uint32_t bhr[4];
                uint32_t bd = bH + (uint32_t)((wc + jp * 16 + b_r) * ASTRE + k0 + b_kh) * 2;
                LDSM4(bhr, bd);
                // hi pass: 4 independent MMAs
#pragma unroll
                for (int mi = 0; mi < 2; mi++)
#pragma unroll
                    for (int jj = 0; jj < 2; jj++)
                        MMA_F16(acc[mi][jp * 2 + jj], ah[mi],
                                bhr[jj * 2], bhr[jj * 2 + 1]);
                // lo pass: 4 MMAs, each 4 issues after its hi partner
#pragma unroll
                for (int mi = 0; mi < 2; mi++)
#pragma unroll
                    for (int jj = 0; jj < 2; jj++)
                        MMA_F16(acc[mi][jp * 2 + jj], al[mi],
                                bhr[jj * 2], bhr[jj * 2 + 1]);
            }
        }

        if (more) stsA((c + 1) & 1);
    }

    // ---- fused epilogue: +bias, GroupNorm(8ch = one n8 tile), affine, lrelu
    const int qlane = lane & 3;
#pragma unroll
    for (int j = 0; j < 8; j++) {
        const int col = wc + j * 8 + 2 * qlane;
        const float2 bb = *reinterpret_cast<const float2*>(bias + col);
        const float2 gg = *reinterpret_cast<const float2*>(gamma + col);
        const float2 be = *reinterpret_cast<const float2*>(beta + col);
#pragma unroll
        for (int mi = 0; mi < 2; mi++) {
            float v0 = acc[mi][j][0] + bb.x;
            float v1 = acc[mi][j][1] + bb.y;
            float v2 = acc[mi][j][2] + bb.x;
            float v3 = acc[mi][j][3] + bb.y;

            float s0 = v0 + v1,           s1 = v2 + v3;
            float t0 = v0 * v0 + v1 * v1, t1 = v2 * v2 + v3 * v3;
            s0 += __shfl_xor_sync(0xffffffffu, s0, 1);
            s0 += __shfl_xor_sync(0xffffffffu, s0, 2);
            s1 += __shfl_xor_sync(0xffffffffu, s1, 1);
            s1 += __shfl_xor_sync(0xffffffffu, s1, 2);
            t0 += __shfl_xor_sync(0xffffffffu, t0, 1);
            t0 += __shfl_xor_sync(0xffffffffu, t0, 2);
            t1 += __shfl_xor_sync(0xffffffffu, t1, 1);
            t1 += __shfl_xor_sync(0xffffffffu, t1, 2);

            const float m0 = s0 * 0.125f, m1 = s1 * 0.125f;
            const float r0 = rsqrtf(fmaxf(t0 * 0.125f - m0 * m0, 0.f) + EPSv);
            const float r1 = rsqrtf(fmaxf(t1 * 0.125f - m1 * m1, 0.f) + EPSv);

            float y0 = (v0 - m0) * r0 * gg.x + be.x;
            float y1 = (v1 - m0) * r0 * gg.y + be.y;
            float y2 = (v2 - m1) * r1 * gg.x + be.x;
            float y3 = (v3 - m1) * r1 * gg.y + be.y;
            y0 = (y0 >= 0.f) ? y0 : SLOPEv * y0;
            y1 = (y1 >= 0.f) ? y1 : SLOPEv * y1;
            y2 = (y2 >= 0.f) ? y2 : SLOPEv * y2;
            y3 = (y3 >= 0.f) ? y3 : SLOPEv * y3;

            const size_t row = (size_t)rowBlk + wr + mi * 16 + (lane >> 2);
            *reinterpret_cast<float2*>(Odst + row * COUT + col) =
                make_float2(y0, y1);
            *reinterpret_cast<float2*>(Odst + (row + 8) * COUT + col) =
                make_float2(y2, y3);
        }
    }
}

extern "C" void kernel_launch(void* const* d_in, const int* in_sizes, int n_in,
                              void* d_out, int out_size)
{
    (void)in_sizes; (void)n_in; (void)out_size;
    const float* query   = (const float*)d_in[0];
    const float* support = (const float*)d_in[1];
    const int*   idx     = (const int*)d_in[2];
    const float* W1  = (const float*)d_in[3];
    const float* b1  = (const float*)d_in[4];
    const float* g1  = (const float*)d_in[5];
    const float* be1 = (const float*)d_in[6];
    const float* W2  = (const float*)d_in[7];
    const float* b2  = (const float*)d_in[8];
    const float* g2  = (const float*)d_in[9];
    const float* be2 = (const float*)d_in[10];
    const float* W3  = (const float*)d_in[11];
    const float* b3  = (const float*)d_in[12];
    const float* g3  = (const float*)d_in[13];
    const float* be3 = (const float*)d_in[14];
    float* out = (float*)d_out;

    split_w_kernel<<<CIN,  COUT>>>(W1, 0);
    split_w_kernel<<<COUT, COUT>>>(W2, 1);
    split_w_kernel<<<COUT, COUT>>>(W3, 2);

    cudaFuncSetAttribute(layer_kernel<0>,
        cudaFuncAttributeMaxDynamicSharedMemorySize, (int)SMEM_DYN);
    cudaFuncSetAttribute(layer_kernel<1>,
        cudaFuncAttributeMaxDynamicSharedMemorySize, (int)SMEM_DYN);
    cudaFuncSetAttribute(layer_kernel<2>,
        cudaFuncAttributeMaxDynamicSharedMemorySize, (int)SMEM_DYN);

    layer_kernel<0><<<ROWS12 / TILE_M, 512, SMEM_DYN>>>(
        support, b1, g1, be1, nullptr, nullptr);
    layer_kernel<1><<<ROWS12 / TILE_M, 512, SMEM_DYN>>>(
        nullptr, b2, g2, be2, nullptr, nullptr);
    layer_kernel<2><<<ROWS3 / TILE_M, 512, SMEM_DYN>>>(
        query, b3, g3, be3, idx, out);
}

// round 9
// speedup vs baseline: 1.9438x; 1.3190x over previous
#include <cuda_runtime.h>
#include <cuda_fp16.h>
#include <cstdint>

// ---------------------------------------------------------------------------
// Upsampling_77214922047593 — legacy mma.sync fp16 single-pass (sm_103 base).
//   h1 = unary(support @ W1)            65536 rows, K=512
//   h2 = unary(h1 @ W2)                 65536 rows, K=256
//   out = unary((gather(h2)+query)@W3)  262144 rows, K=256
// A and B both rounded to fp16, ONE MMA pass on mma.sync.m16n8k16.f16/f32
// (fp32 accumulate). Measured error calibration: B-rounding alone = 3.05e-4;
// A+B rounding ~ sqrt(2)x = ~4.3e-4 < 1e-3 bound.
// CTA 128x256, 512 thr (16 warps, warp 32x64), KC=64 double-buffered smem,
// cp.async fp16 weights (pre-rounded+transposed), fused GroupNorm(32 groups
// of 8) + affine + leaky-relu epilogue.
// ---------------------------------------------------------------------------

namespace {
constexpr int Mm   = 16384;
constexpr int CIN  = 512;
constexpr int COUT = 256;
constexpr float EPSv   = 1e-5f;
constexpr float SLOPEv = 0.1f;

constexpr int ROWS12 = 65536;
constexpr int ROWS3  = 262144;

constexpr int TILE_M = 128;
constexpr int KC     = 64;         // K per smem chunk
constexpr int ASTRE  = 72;         // padded row stride in fp16 elems (144B)

constexpr int A_BYTES   = TILE_M * ASTRE * 2;   // 18432 (hi only)
constexpr int B_BYTES   = COUT   * ASTRE * 2;   // 36864 (hi only)
constexpr int BUF_BYTES = A_BYTES + B_BYTES;          // 55296
constexpr size_t SMEM_DYN = 2 * (size_t)BUF_BYTES;    // 110592
} // namespace

__device__ float g_h1[(size_t)ROWS12 * COUT];
__device__ float g_h2[(size_t)ROWS12 * COUT];
// pre-rounded, pre-transposed weights: Wt[layer][n][k], fp16
__device__ __half g_Wth[3][COUT][CIN];

// ---------------- helpers ----------------
__device__ __forceinline__ uint32_t smem_u32(const void* p) {
    uint32_t a;
    asm("{ .reg .u64 t; cvta.to.shared.u64 t, %1; cvt.u32.u64 %0, t; }"
        : "=r"(a) : "l"(p));
    return a;
}

#define LDSM4(r, addr)                                                         \
    asm volatile("ldmatrix.sync.aligned.m8n8.x4.shared.b16 {%0,%1,%2,%3}, [%4];" \
        : "=r"((r)[0]), "=r"((r)[1]), "=r"((r)[2]), "=r"((r)[3]) : "r"(addr))

#define MMA_F16(c, a, b0, b1)                                                  \
    asm volatile("mma.sync.aligned.m16n8k16.row.col.f32.f16.f16.f32 "          \
        "{%0,%1,%2,%3}, {%4,%5,%6,%7}, {%8,%9}, {%0,%1,%2,%3};"                \
        : "+f"((c)[0]), "+f"((c)[1]), "+f"((c)[2]), "+f"((c)[3])               \
        : "r"((a)[0]), "r"((a)[1]), "r"((a)[2]), "r"((a)[3]),                  \
          "r"(b0), "r"(b1))

#define CP_ASYNC8(dst, src)                                                    \
    asm volatile("cp.async.ca.shared.global [%0], [%1], 8;"                    \
        :: "r"(dst), "l"(src))
#define CP_COMMIT() asm volatile("cp.async.commit_group;" ::: "memory")
#define CP_WAIT0()  asm volatile("cp.async.wait_group 0;" ::: "memory")

// round float4 to fp16 packed words
__device__ __forceinline__ void round4h(float4 v, uint32_t h[2]) {
    __half2 h01 = __floats2half2_rn(v.x, v.y);
    __half2 h23 = __floats2half2_rn(v.z, v.w);
    h[0] = *reinterpret_cast<uint32_t*>(&h01);
    h[1] = *reinterpret_cast<uint32_t*>(&h23);
}

// ---------------- weight prologue: round + transpose ----------------
__global__ void split_w_kernel(const float* __restrict__ W, int layer) {
    int k = blockIdx.x;
    int n = threadIdx.x;
    g_Wth[layer][n][k] = __float2half_rn(W[(size_t)k * COUT + n]);
}

// ---------------- main fused layer ----------------
// MODE 0: support (K=512) -> g_h1 ; MODE 1: g_h1 -> g_h2 ;
// MODE 2: query + gather(g_h2) -> out
template <int MODE>
__global__ void __launch_bounds__(512, 1)
layer_kernel(const float* __restrict__ Aext,
             const float* __restrict__ bias,
             const float* __restrict__ gamma,
             const float* __restrict__ beta,
             const int*   __restrict__ idx,
             float*       __restrict__ Oext)
{
    constexpr int K     = (MODE == 0) ? CIN : COUT;
    constexpr int NC    = K / KC;
    constexpr int LAYER = MODE;

    extern __shared__ __align__(16) char smc[];
    __shared__ int s_grow[TILE_M];

    const int tid  = threadIdx.x;
    const int wid  = tid >> 5;
    const int lane = tid & 31;
    const int rowBlk = blockIdx.x * TILE_M;

    const float* Asrc = (MODE == 1) ? g_h1 : Aext;
    float*       Odst = (MODE == 0) ? g_h1 : ((MODE == 1) ? g_h2 : Oext);

    const __half* Wth = &g_Wth[LAYER][0][0];

    const uint32_t sbase = smem_u32(smc);

    if (MODE == 2) {
        if (tid < TILE_M) {
            int grow = rowBlk + tid;
            s_grow[tid] = (grow >> 16) * Mm + idx[grow];
        }
        __syncthreads();
    }

    // ---- staging ----
    // A: 128 x 64 fp32 -> 2048 float4, 512 threads -> 4 each
    float4 vpipe[4];
    auto ldgA = [&](int kc) {
#pragma unroll
        for (int i = 0; i < 4; i++) {
            int s  = tid + i * 512;
            int r  = s >> 4;
            int c4 = (s & 15) * 4;
            if (MODE == 2) {
                float4 q = *(const float4*)(Aext + (size_t)(rowBlk + r) * COUT + kc + c4);
                float4 g = *(const float4*)(g_h2 + (size_t)s_grow[r] * COUT + kc + c4);
                vpipe[i] = make_float4(q.x + g.x, q.y + g.y, q.z + g.z, q.w + g.w);
            } else {
                vpipe[i] = *(const float4*)(Asrc + (size_t)(rowBlk + r) * K + kc + c4);
            }
        }
    };
    auto stsA = [&](int buf) {
        char* ab = smc + buf * BUF_BYTES;
#pragma unroll
        for (int i = 0; i < 4; i++) {
            int s  = tid + i * 512;
            int r  = s >> 4;
            int c4 = (s & 15) * 4;
            uint32_t h[2];
            round4h(vpipe[i], h);
            int off = (r * ASTRE + c4) * 2;
            *(uint2*)(ab + off) = make_uint2(h[0], h[1]);
        }
    };
    // B: 256 n-rows x 16 8B-segs = 4096 segs / 512 thr = 8 each
    auto cpB = [&](int kc, int buf) {
        uint32_t bh = sbase + buf * BUF_BYTES + A_BYTES;
#pragma unroll
        for (int i = 0; i < 8; i++) {
            int q   = tid + i * 512;          // 0..4095
            int n   = q >> 4;
            int seg = q & 15;
            uint32_t doff = (uint32_t)(n * ASTRE + seg * 4) * 2;
            size_t   soff = (size_t)n * CIN + kc + seg * 4;
            CP_ASYNC8(bh + doff, Wth + soff);
        }
    };

    // ---- warp layout: 16 warps = 4 m-groups x 4 n-groups, warp 32x64 ----
    const int wm = wid & 3;
    const int wn = wid >> 2;
    const int wr = wm * 32;
    const int wc = wn * 64;

    float acc[2][8][4];
#pragma unroll
    for (int mi = 0; mi < 2; mi++)
#pragma unroll
        for (int j = 0; j < 8; j++)
#pragma unroll
            for (int c = 0; c < 4; c++) acc[mi][j][c] = 0.f;

    // ldmatrix lane addressing
    const int a_r  = (lane & 15);
    const int a_kh = (lane >> 4) * 8;
    const int b_r  = ((lane >> 4) & 1) * 8 + (lane & 7);
    const int b_kh = ((lane >> 3) & 1) * 8;

    // ---- prime chunk 0 ----
    ldgA(0);
    cpB(0, 0);
    CP_COMMIT();
    stsA(0);

#pragma unroll 1
    for (int c = 0; c < NC; c++) {
        const int cb = c & 1;
        const bool more = (c + 1 < NC);

        if (more) ldgA((c + 1) * KC);    // LDGs in flight across the wait
        CP_WAIT0();
        __syncthreads();
        if (more) {
            cpB((c + 1) * KC, (c + 1) & 1);
            CP_COMMIT();
        }

        // ---- MMAs on buffer cb: single fp16 pass ----
        const uint32_t aH = sbase + cb * BUF_BYTES;
        const uint32_t bH = aH + A_BYTES;
#pragma unroll
        for (int ks = 0; ks < 4; ks++) {
            const int k0 = ks * 16;
            uint32_t ah[2][4];
#pragma unroll
            for (int mi = 0; mi < 2; mi++) {
                uint32_t ad = aH + (uint32_t)((wr + mi * 16 + a_r) * ASTRE + k0 + a_kh) * 2;
                LDSM4(ah[mi], ad);
            }
#pragma unroll
            for (int jp = 0; jp < 4; jp++) {
                uint32_t bhr[4];
                uint32_t bd = bH + (uint32_t)((wc + jp * 16 + b_r) * ASTRE + k0 + b_kh) * 2;
                LDSM4(bhr, bd);
#pragma unroll
                for (int mi = 0; mi < 2; mi++)
#pragma unroll
                    for (int jj = 0; jj < 2; jj++)
                        MMA_F16(acc[mi][jp * 2 + jj], ah[mi],
                                bhr[jj * 2], bhr[jj * 2 + 1]);
            }
        }

        if (more) stsA((c + 1) & 1);
    }

    // ---- fused epilogue: +bias, GroupNorm(8ch = one n8 tile), affine, lrelu
    const int qlane = lane & 3;
#pragma unroll
    for (int j = 0; j < 8; j++) {
        const int col = wc + j * 8 + 2 * qlane;
        const float2 bb = *reinterpret_cast<const float2*>(bias + col);
        const float2 gg = *reinterpret_cast<const float2*>(gamma + col);
        const float2 be = *reinterpret_cast<const float2*>(beta + col);
#pragma unroll
        for (int mi = 0; mi < 2; mi++) {
            float v0 = acc[mi][j][0] + bb.x;
            float v1 = acc[mi][j][1] + bb.y;
            float v2 = acc[mi][j][2] + bb.x;
            float v3 = acc[mi][j][3] + bb.y;

            float s0 = v0 + v1,           s1 = v2 + v3;
            float t0 = v0 * v0 + v1 * v1, t1 = v2 * v2 + v3 * v3;
            s0 += __shfl_xor_sync(0xffffffffu, s0, 1);
            s0 += __shfl_xor_sync(0xffffffffu, s0, 2);
            s1 += __shfl_xor_sync(0xffffffffu, s1, 1);
            s1 += __shfl_xor_sync(0xffffffffu, s1, 2);
            t0 += __shfl_xor_sync(0xffffffffu, t0, 1);
            t0 += __shfl_xor_sync(0xffffffffu, t0, 2);
            t1 += __shfl_xor_sync(0xffffffffu, t1, 1);
            t1 += __shfl_xor_sync(0xffffffffu, t1, 2);

            const float m0 = s0 * 0.125f, m1 = s1 * 0.125f;
            const float r0 = rsqrtf(fmaxf(t0 * 0.125f - m0 * m0, 0.f) + EPSv);
            const float r1 = rsqrtf(fmaxf(t1 * 0.125f - m1 * m1, 0.f) + EPSv);

            float y0 = (v0 - m0) * r0 * gg.x + be.x;
            float y1 = (v1 - m0) * r0 * gg.y + be.y;
            float y2 = (v2 - m1) * r1 * gg.x + be.x;
            float y3 = (v3 - m1) * r1 * gg.y + be.y;
            y0 = (y0 >= 0.f) ? y0 : SLOPEv * y0;
            y1 = (y1 >= 0.f) ? y1 : SLOPEv * y1;
            y2 = (y2 >= 0.f) ? y2 : SLOPEv * y2;
            y3 = (y3 >= 0.f) ? y3 : SLOPEv * y3;

            const size_t row = (size_t)rowBlk + wr + mi * 16 + (lane >> 2);
            *reinterpret_cast<float2*>(Odst + row * COUT + col) =
                make_float2(y0, y1);
            *reinterpret_cast<float2*>(Odst + (row + 8) * COUT + col) =
                make_float2(y2, y3);
        }
    }
}

extern "C" void kernel_launch(void* const* d_in, const int* in_sizes, int n_in,
                              void* d_out, int out_size)
{
    (void)in_sizes; (void)n_in; (void)out_size;
    const float* query   = (const float*)d_in[0];
    const float* support = (const float*)d_in[1];
    const int*   idx     = (const int*)d_in[2];
    const float* W1  = (const float*)d_in[3];
    const float* b1  = (const float*)d_in[4];
    const float* g1  = (const float*)d_in[5];
    const float* be1 = (const float*)d_in[6];
    const float* W2  = (const float*)d_in[7];
    const float* b2  = (const float*)d_in[8];
    const float* g2  = (const float*)d_in[9];
    const float* be2 = (const float*)d_in[10];
    const float* W3  = (const float*)d_in[11];
    const float* b3  = (const float*)d_in[12];
    const float* g3  = (const float*)d_in[13];
    const float* be3 = (const float*)d_in[14];
    float* out = (float*)d_out;

    split_w_kernel<<<CIN,  COUT>>>(W1, 0);
    split_w_kernel<<<COUT, COUT>>>(W2, 1);
    split_w_kernel<<<COUT, COUT>>>(W3, 2);

    cudaFuncSetAttribute(layer_kernel<0>,
        cudaFuncAttributeMaxDynamicSharedMemorySize, (int)SMEM_DYN);
    cudaFuncSetAttribute(layer_kernel<1>,
        cudaFuncAttributeMaxDynamicSharedMemorySize, (int)SMEM_DYN);
    cudaFuncSetAttribute(layer_kernel<2>,
        cudaFuncAttributeMaxDynamicSharedMemorySize, (int)SMEM_DYN);

    layer_kernel<0><<<ROWS12 / TILE_M, 512, SMEM_DYN>>>(
        support, b1, g1, be1, nullptr, nullptr);
    layer_kernel<1><<<ROWS12 / TILE_M, 512, SMEM_DYN>>>(
        nullptr, b2, g2, be2, nullptr, nullptr);
    layer_kernel<2><<<ROWS3 / TILE_M, 512, SMEM_DYN>>>(
        query, b3, g3, be3, idx, out);
}

// round 10
// speedup vs baseline: 2.1534x; 1.1079x over previous
#include <cuda_runtime.h>
#include <cuda_fp16.h>
#include <cstdint>

// ---------------------------------------------------------------------------
// Upsampling_77214922047593 — legacy mma.sync fp16 single-pass (sm_103 base).
// R9->R10:
//  * Layers 1+2 FUSED in one kernel: CTA computes full 128x256 h1 tile,
//    GroupNorm epilogue in regs, rounds fp16 straight into smem A-layout of
//    GEMM-2 (h1 never touches DRAM), then GEMM-2 + epilogue -> h2.
//  * h2 stored fp16 (gather traffic halved; one extra rounding, calibrated
//    ~5e-4 total, under 1e-3).
//   fused:  h2 = unary(unary(support @ W1) @ W2)     65536 rows
//   layer3: out = unary((gather(h2)+query) @ W3)     262144 rows
// ---------------------------------------------------------------------------

namespace {
constexpr int Mm   = 16384;
constexpr int CIN  = 512;
constexpr int COUT = 256;
constexpr float EPSv   = 1e-5f;
constexpr float SLOPEv = 0.1f;

constexpr int ROWS12 = 65536;
constexpr int ROWS3  = 262144;

constexpr int TILE_M = 128;
constexpr int KC     = 64;         // K per smem chunk
constexpr int ASTRE  = 72;         // padded row stride in fp16 elems (144B)

constexpr int A_BYTES   = TILE_M * ASTRE * 2;   // 18432
constexpr int B_BYTES   = COUT   * ASTRE * 2;   // 36864
// fused kernel: A1 double buf + B double buf + A2 (4 chunks, h1 tile)
constexpr size_t SMEM_F = 2 * (size_t)A_BYTES + 2 * B_BYTES + 4 * A_BYTES; // 184320
// layer-3 kernel: (A + B) double buffered
constexpr size_t SMEM_3 = 2 * ((size_t)A_BYTES + B_BYTES);                 // 110592
} // namespace

__device__ __half g_h2f[(size_t)ROWS12 * COUT];     // fp16 h2 (32 MB)
// pre-rounded, pre-transposed weights: Wt[layer][n][k], fp16
__device__ __half g_Wth[3][COUT][CIN];

// ---------------- helpers ----------------
__device__ __forceinline__ uint32_t smem_u32(const void* p) {
    uint32_t a;
    asm("{ .reg .u64 t; cvta.to.shared.u64 t, %1; cvt.u32.u64 %0, t; }"
        : "=r"(a) : "l"(p));
    return a;
}

#define LDSM4(r, addr)                                                         \
    asm volatile("ldmatrix.sync.aligned.m8n8.x4.shared.b16 {%0,%1,%2,%3}, [%4];" \
        : "=r"((r)[0]), "=r"((r)[1]), "=r"((r)[2]), "=r"((r)[3]) : "r"(addr))

#define MMA_F16(c, a, b0, b1)                                                  \
    asm volatile("mma.sync.aligned.m16n8k16.row.col.f32.f16.f16.f32 "          \
        "{%0,%1,%2,%3}, {%4,%5,%6,%7}, {%8,%9}, {%0,%1,%2,%3};"                \
        : "+f"((c)[0]), "+f"((c)[1]), "+f"((c)[2]), "+f"((c)[3])               \
        : "r"((a)[0]), "r"((a)[1]), "r"((a)[2]), "r"((a)[3]),                  \
          "r"(b0), "r"(b1))

#define CP_ASYNC8(dst, src)                                                    \
    asm volatile("cp.async.ca.shared.global [%0], [%1], 8;"                    \
        :: "r"(dst), "l"(src))
#define CP_COMMIT() asm volatile("cp.async.commit_group;" ::: "memory")
#define CP_WAIT0()  asm volatile("cp.async.wait_group 0;" ::: "memory")

__device__ __forceinline__ void round4h(float4 v, uint32_t h[2]) {
    __half2 h01 = __floats2half2_rn(v.x, v.y);
    __half2 h23 = __floats2half2_rn(v.z, v.w);
    h[0] = *reinterpret_cast<uint32_t*>(&h01);
    h[1] = *reinterpret_cast<uint32_t*>(&h23);
}

// GroupNorm-of-8 + affine + leaky-relu on the 4 acc values of one n8 tile.
// (acc layout: v0,v1 in group g0 rows r, v2,v3 same cols rows r+8)
__device__ __forceinline__ void gn8(float v0, float v1, float v2, float v3,
                                    float2 gg, float2 be,
                                    float& y0, float& y1, float& y2, float& y3)
{
    float s0 = v0 + v1,           s1 = v2 + v3;
    float t0 = v0 * v0 + v1 * v1, t1 = v2 * v2 + v3 * v3;
    s0 += __shfl_xor_sync(0xffffffffu, s0, 1);
    s0 += __shfl_xor_sync(0xffffffffu, s0, 2);
    s1 += __shfl_xor_sync(0xffffffffu, s1, 1);
    s1 += __shfl_xor_sync(0xffffffffu, s1, 2);
    t0 += __shfl_xor_sync(0xffffffffu, t0, 1);
    t0 += __shfl_xor_sync(0xffffffffu, t0, 2);
    t1 += __shfl_xor_sync(0xffffffffu, t1, 1);
    t1 += __shfl_xor_sync(0xffffffffu, t1, 2);
    const float m0 = s0 * 0.125f, m1 = s1 * 0.125f;
    const float r0 = rsqrtf(fmaxf(t0 * 0.125f - m0 * m0, 0.f) + EPSv);
    const float r1 = rsqrtf(fmaxf(t1 * 0.125f - m1 * m1, 0.f) + EPSv);
    y0 = (v0 - m0) * r0 * gg.x + be.x;
    y1 = (v1 - m0) * r0 * gg.y + be.y;
    y2 = (v2 - m1) * r1 * gg.x + be.x;
    y3 = (v3 - m1) * r1 * gg.y + be.y;
    y0 = (y0 >= 0.f) ? y0 : SLOPEv * y0;
    y1 = (y1 >= 0.f) ? y1 : SLOPEv * y1;
    y2 = (y2 >= 0.f) ? y2 : SLOPEv * y2;
    y3 = (y3 >= 0.f) ? y3 : SLOPEv * y3;
}

// ---------------- weight prologue: round + transpose ----------------
__global__ void split_w_kernel(const float* __restrict__ W, int layer) {
    int k = blockIdx.x;
    int n = threadIdx.x;
    g_Wth[layer][n][k] = __float2half_rn(W[(size_t)k * COUT + n]);
}

// ---------------- fused layers 1+2 ----------------
__global__ void __launch_bounds__(512, 1)
fused12_kernel(const float* __restrict__ support,
               const float* __restrict__ b1, const float* __restrict__ g1,
               const float* __restrict__ be1,
               const float* __restrict__ b2, const float* __restrict__ g2,
               const float* __restrict__ be2)
{
    constexpr int NC1 = CIN / KC;    // 8
    constexpr int NC2 = COUT / KC;   // 4

    extern __shared__ __align__(16) char smc[];
    const uint32_t sbase  = smem_u32(smc);
    const uint32_t bBase  = sbase + 2 * A_BYTES;
    const uint32_t a2Base = bBase + 2 * B_BYTES;
    char* a2c = smc + 2 * A_BYTES + 2 * B_BYTES;

    const int tid  = threadIdx.x;
    const int wid  = tid >> 5;
    const int lane = tid & 31;
    const int rowBlk = blockIdx.x * TILE_M;

    const __half* W1h = &g_Wth[0][0][0];
    const __half* W2h = &g_Wth[1][0][0];

    // ---- staging ----
    float4 vpipe[4];
    auto ldgA1 = [&](int kc) {
#pragma unroll
        for (int i = 0; i < 4; i++) {
            int s  = tid + i * 512;
            int r  = s >> 4;
            int c4 = (s & 15) * 4;
            vpipe[i] = *(const float4*)(support + (size_t)(rowBlk + r) * CIN + kc + c4);
        }
    };
    auto stsA1 = [&](int buf) {
        char* ab = smc + buf * A_BYTES;
#pragma unroll
        for (int i = 0; i < 4; i++) {
            int s  = tid + i * 512;
            int r  = s >> 4;
            int c4 = (s & 15) * 4;
            uint32_t h[2];
            round4h(vpipe[i], h);
            *(uint2*)(ab + (r * ASTRE + c4) * 2) = make_uint2(h[0], h[1]);
        }
    };
    auto cpB = [&](const __half* Wsrc, int kc, int buf) {
        uint32_t bh = bBase + buf * B_BYTES;
#pragma unroll
        for (int i = 0; i < 8; i++) {
            int q   = tid + i * 512;
            int n   = q >> 4;
            int seg = q & 15;
            CP_ASYNC8(bh + (uint32_t)(n * ASTRE + seg * 4) * 2,
                      Wsrc + (size_t)n * CIN + kc + seg * 4);
        }
    };

    // ---- warp layout ----
    const int wm = wid & 3;
    const int wn = wid >> 2;
    const int wr = wm * 32;
    const int wc = wn * 64;
    const int qlane = lane & 3;

    float acc[2][8][4];
#pragma unroll
    for (int mi = 0; mi < 2; mi++)
#pragma unroll
        for (int j = 0; j < 8; j++)
#pragma unroll
            for (int c = 0; c < 4; c++) acc[mi][j][c] = 0.f;

    const int a_r  = (lane & 15);
    const int a_kh = (lane >> 4) * 8;
    const int b_r  = ((lane >> 4) & 1) * 8 + (lane & 7);
    const int b_kh = ((lane >> 3) & 1) * 8;

    // ================= GEMM 1 (K=512) =================
    ldgA1(0);
    cpB(W1h, 0, 0);
    CP_COMMIT();
    stsA1(0);

#pragma unroll 1
    for (int c = 0; c < NC1; c++) {
        const int cb = c & 1;
        const bool more = (c + 1 < NC1);
        if (more) ldgA1((c + 1) * KC);
        CP_WAIT0();
        __syncthreads();
        if (more) { cpB(W1h, (c + 1) * KC, (c + 1) & 1); CP_COMMIT(); }

        const uint32_t aH = sbase + cb * A_BYTES;
        const uint32_t bH = bBase + cb * B_BYTES;
#pragma unroll
        for (int ks = 0; ks < 4; ks++) {
            const int k0 = ks * 16;
            uint32_t ah[2][4];
#pragma unroll
            for (int mi = 0; mi < 2; mi++)
                LDSM4(ah[mi], aH + (uint32_t)((wr + mi * 16 + a_r) * ASTRE + k0 + a_kh) * 2);
#pragma unroll
            for (int jp = 0; jp < 4; jp++) {
                uint32_t bhr[4];
                LDSM4(bhr, bH + (uint32_t)((wc + jp * 16 + b_r) * ASTRE + k0 + b_kh) * 2);
#pragma unroll
                for (int mi = 0; mi < 2; mi++)
#pragma unroll
                    for (int jj = 0; jj < 2; jj++)
                        MMA_F16(acc[mi][jp * 2 + jj], ah[mi],
                                bhr[jj * 2], bhr[jj * 2 + 1]);
            }
        }
        if (more) stsA1((c + 1) & 1);
    }

    // prefetch GEMM-2 B chunk 0 under the epilogue
    cpB(W2h, 0, 0);
    CP_COMMIT();

    // ---- epilogue 1: GN -> fp16 h1 tile into A2 smem (chunked layout) ----
    // col = wc + j*8 + 2*qlane lies in chunk wn, within-chunk kk = j*8+2*qlane
#pragma unroll
    for (int j = 0; j < 8; j++) {
        const int col = wc + j * 8 + 2 * qlane;
        const int kk  = j * 8 + 2 * qlane;
        const float2 bb = *reinterpret_cast<const float2*>(b1 + col);
        const float2 gg = *reinterpret_cast<const float2*>(g1 + col);
        const float2 be = *reinterpret_cast<const float2*>(be1 + col);
#pragma unroll
        for (int mi = 0; mi < 2; mi++) {
            float y0, y1, y2, y3;
            gn8(acc[mi][j][0] + bb.x, acc[mi][j][1] + bb.y,
                acc[mi][j][2] + bb.x, acc[mi][j][3] + bb.y, gg, be,
                y0, y1, y2, y3);
            const int row0 = wr + mi * 16 + (lane >> 2);
            __half2 p0 = __floats2half2_rn(y0, y1);
            __half2 p1 = __floats2half2_rn(y2, y3);
            *(__half2*)(a2c + wn * A_BYTES + (row0 * ASTRE + kk) * 2)       = p0;
            *(__half2*)(a2c + wn * A_BYTES + ((row0 + 8) * ASTRE + kk) * 2) = p1;
        }
    }

#pragma unroll
    for (int mi = 0; mi < 2; mi++)
#pragma unroll
        for (int j = 0; j < 8; j++)
#pragma unroll
            for (int c = 0; c < 4; c++) acc[mi][j][c] = 0.f;

    __syncthreads();   // A2 visible to all warps

    // ================= GEMM 2 (K=256, A resident in smem) =================
#pragma unroll 1
    for (int c = 0; c < NC2; c++) {
        const int cb = c & 1;
        const bool more = (c + 1 < NC2);
        CP_WAIT0();
        __syncthreads();
        if (more) { cpB(W2h, (c + 1) * KC, (c + 1) & 1); CP_COMMIT(); }

        const uint32_t aH = a2Base + c * A_BYTES;
        const uint32_t bH = bBase + cb * B_BYTES;
#pragma unroll
        for (int ks = 0; ks < 4; ks++) {
            const int k0 = ks * 16;
            uint32_t ah[2][4];
#pragma unroll
            for (int mi = 0; mi < 2; mi++)
                LDSM4(ah[mi], aH + (uint32_t)((wr + mi * 16 + a_r) * ASTRE + k0 + a_kh) * 2);
#pragma unroll
            for (int jp = 0; jp < 4; jp++) {
                uint32_t bhr[4];
                LDSM4(bhr, bH + (uint32_t)((wc + jp * 16 + b_r) * ASTRE + k0 + b_kh) * 2);
#pragma unroll
                for (int mi = 0; mi < 2; mi++)
#pragma unroll
                    for (int jj = 0; jj < 2; jj++)
                        MMA_F16(acc[mi][jp * 2 + jj], ah[mi],
                                bhr[jj * 2], bhr[jj * 2 + 1]);
            }
        }
    }

    // ---- epilogue 2: GN -> fp16 h2 to global ----
#pragma unroll
    for (int j = 0; j < 8; j++) {
        const int col = wc + j * 8 + 2 * qlane;
        const float2 bb = *reinterpret_cast<const float2*>(b2 + col);
        const float2 gg = *reinterpret_cast<const float2*>(g2 + col);
        const float2 be = *reinterpret_cast<const float2*>(be2 + col);
#pragma unroll
        for (int mi = 0; mi < 2; mi++) {
            float y0, y1, y2, y3;
            gn8(acc[mi][j][0] + bb.x, acc[mi][j][1] + bb.y,
                acc[mi][j][2] + bb.x, acc[mi][j][3] + bb.y, gg, be,
                y0, y1, y2, y3);
            const size_t row = (size_t)rowBlk + wr + mi * 16 + (lane >> 2);
            *(__half2*)(g_h2f + row * COUT + col)       = __floats2half2_rn(y0, y1);
            *(__half2*)(g_h2f + (row + 8) * COUT + col) = __floats2half2_rn(y2, y3);
        }
    }
}

// ---------------- layer 3: out = unary((gather(h2)+query) @ W3) ----------------
__global__ void __launch_bounds__(512, 1)
layer3_kernel(const float* __restrict__ query,
              const float* __restrict__ b3, const float* __restrict__ g3,
              const float* __restrict__ be3,
              const int*   __restrict__ idx,
              float*       __restrict__ out)
{
    constexpr int NC = COUT / KC;   // 4

    extern __shared__ __align__(16) char smc[];
    __shared__ int s_grow[TILE_M];

    const uint32_t sbase = smem_u32(smc);
    const int tid  = threadIdx.x;
    const int wid  = tid >> 5;
    const int lane = tid & 31;
    const int rowBlk = blockIdx.x * TILE_M;

    const __half* W3h = &g_Wth[2][0][0];
    constexpr int BUF_BYTES3 = A_BYTES + B_BYTES;

    if (tid < TILE_M) {
        int grow = rowBlk + tid;
        s_grow[tid] = (grow >> 16) * Mm + idx[grow];
    }
    __syncthreads();

    float4 vpipe[4];
    auto ldgA = [&](int kc) {
#pragma unroll
        for (int i = 0; i < 4; i++) {
            int s  = tid + i * 512;
            int r  = s >> 4;
            int c4 = (s & 15) * 4;
            float4 q = *(const float4*)(query + (size_t)(rowBlk + r) * COUT + kc + c4);
            uint2 gv = *(const uint2*)(g_h2f + (size_t)s_grow[r] * COUT + kc + c4);
            float2 ga = __half22float2(*reinterpret_cast<__half2*>(&gv.x));
            float2 gb = __half22float2(*reinterpret_cast<__half2*>(&gv.y));
            vpipe[i] = make_float4(q.x + ga.x, q.y + ga.y, q.z + gb.x, q.w + gb.y);
        }
    };
    auto stsA = [&](int buf) {
        char* ab = smc + buf * BUF_BYTES3;
#pragma unroll
        for (int i = 0; i < 4; i++) {
            int s  = tid + i * 512;
            int r  = s >> 4;
            int c4 = (s & 15) * 4;
            uint32_t h[2];
            round4h(vpipe[i], h);
            *(uint2*)(ab + (r * ASTRE + c4) * 2) = make_uint2(h[0], h[1]);
        }
    };
    auto cpB = [&](int kc, int buf) {
        uint32_t bh = sbase + buf * BUF_BYTES3 + A_BYTES;
#pragma unroll
        for (int i = 0; i < 8; i++) {
            int q   = tid + i * 512;
            int n   = q >> 4;
            int seg = q & 15;
            CP_ASYNC8(bh + (uint32_t)(n * ASTRE + seg * 4) * 2,
                      W3h + (size_t)n * CIN + kc + seg * 4);
        }
    };

    const int wm = wid & 3;
    const int wn = wid >> 2;
    const int wr = wm * 32;
    const int wc = wn * 64;
    const int qlane = lane & 3;

    float acc[2][8][4];
#pragma unroll
    for (int mi = 0; mi < 2; mi++)
#pragma unroll
        for (int j = 0; j < 8; j++)
#pragma unroll
            for (int c = 0; c < 4; c++) acc[mi][j][c] = 0.f;

    const int a_r  = (lane & 15);
    const int a_kh = (lane >> 4) * 8;
    const int b_r  = ((lane >> 4) & 1) * 8 + (lane & 7);
    const int b_kh = ((lane >> 3) & 1) * 8;

    ldgA(0);
    cpB(0, 0);
    CP_COMMIT();
    stsA(0);

#pragma unroll 1
    for (int c = 0; c < NC; c++) {
        const int cb = c & 1;
        const bool more = (c + 1 < NC);
        if (more) ldgA((c + 1) * KC);
        CP_WAIT0();
        __syncthreads();
        if (more) { cpB((c + 1) * KC, (c + 1) & 1); CP_COMMIT(); }

        const uint32_t aH = sbase + cb * BUF_BYTES3;
        const uint32_t bH = aH + A_BYTES;
#pragma unroll
        for (int ks = 0; ks < 4; ks++) {
            const int k0 = ks * 16;
            uint32_t ah[2][4];
#pragma unroll
            for (int mi = 0; mi < 2; mi++)
                LDSM4(ah[mi], aH + (uint32_t)((wr + mi * 16 + a_r) * ASTRE + k0 + a_kh) * 2);
#pragma unroll
            for (int jp = 0; jp < 4; jp++) {
                uint32_t bhr[4];
                LDSM4(bhr, bH + (uint32_t)((wc + jp * 16 + b_r) * ASTRE + k0 + b_kh) * 2);
#pragma unroll
                for (int mi = 0; mi < 2; mi++)
#pragma unroll
                    for (int jj = 0; jj < 2; jj++)
                        MMA_F16(acc[mi][jp * 2 + jj], ah[mi],
                                bhr[jj * 2], bhr[jj * 2 + 1]);
            }
        }
        if (more) stsA((c + 1) & 1);
    }

    // ---- epilogue: GN -> fp32 out ----
#pragma unroll
    for (int j = 0; j < 8; j++) {
        const int col = wc + j * 8 + 2 * qlane;
        const float2 bb = *reinterpret_cast<const float2*>(b3 + col);
        const float2 gg = *reinterpret_cast<const float2*>(g3 + col);
        const float2 be = *reinterpret_cast<const float2*>(be3 + col);
#pragma unroll
        for (int mi = 0; mi < 2; mi++) {
            float y0, y1, y2, y3;
            gn8(acc[mi][j][0] + bb.x, acc[mi][j][1] + bb.y,
                acc[mi][j][2] + bb.x, acc[mi][j][3] + bb.y, gg, be,
                y0, y1, y2, y3);
            const size_t row = (size_t)rowBlk + wr + mi * 16 + (lane >> 2);
            *reinterpret_cast<float2*>(out + row * COUT + col) =
                make_float2(y0, y1);
            *reinterpret_cast<float2*>(out + (row + 8) * COUT + col) =
                make_float2(y2, y3);
        }
    }
}

extern "C" void kernel_launch(void* const* d_in, const int* in_sizes, int n_in,
                              void* d_out, int out_size)
{
    (void)in_sizes; (void)n_in; (void)out_size;
    const float* query   = (const float*)d_in[0];
    const float* support = (const float*)d_in[1];
    const int*   idx     = (const int*)d_in[2];
    const float* W1  = (const float*)d_in[3];
    const float* b1  = (const float*)d_in[4];
    const float* g1  = (const float*)d_in[5];
    const float* be1 = (const float*)d_in[6];
    const float* W2  = (const float*)d_in[7];
    const float* b2  = (const float*)d_in[8];
    const float* g2  = (const float*)d_in[9];
    const float* be2 = (const float*)d_in[10];
    const float* W3  = (const float*)d_in[11];
    const float* b3  = (const float*)d_in[12];
    const float* g3  = (const float*)d_in[13];
    const float* be3 = (const float*)d_in[14];
    float* out = (float*)d_out;

    split_w_kernel<<<CIN,  COUT>>>(W1, 0);
    split_w_kernel<<<COUT, COUT>>>(W2, 1);
    split_w_kernel<<<COUT, COUT>>>(W3, 2);

    cudaFuncSetAttribute(fused12_kernel,
        cudaFuncAttributeMaxDynamicSharedMemorySize, (int)SMEM_F);
    cudaFuncSetAttribute(layer3_kernel,
        cudaFuncAttributeMaxDynamicSharedMemorySize, (int)SMEM_3);

    fused12_kernel<<<ROWS12 / TILE_M, 512, SMEM_F>>>(
        support, b1, g1, be1, b2, g2, be2);
    layer3_kernel<<<ROWS3 / TILE_M, 512, SMEM_3>>>(
        query, b3, g3, be3, idx, out);
}